// round 11
// baseline (speedup 1.0000x reference)
#include <cuda_runtime.h>
#include <cuda_bf16.h>
#include <cstdint>

// Problem constants
#define BN   32
#define DN   256
#define KN   1024
#define HWN  1024
#define NN   32768

#define CAND_MAX 48
#define MARGIN   4.0e-3f   // > 2x worst-case bf16 d2 error

#define AS 544             // A tile row stride bytes (512 data + 32 pad)

// ---------------------------------------------------------------------------
// Device-global scratch (no allocation allowed)
__device__ unsigned long long g_best[NN];
__device__ float g_w2[KN];
__device__ float g_x2[NN];
__device__ float g_cminF[NN];                 // per-query global approx min
__device__ __nv_bfloat16 g_xb[NN * DN];       // x transposed bf16 [n][d]
__device__ float g_xt[NN * DN];               // x transposed fp32 [n][d]
__device__ int g_ccnt[NN];
__device__ uint2 g_cand[NN * CAND_MAX];       // (approx d2 bits, code idx)
__device__ uint2 g_bf[8 * 16 * 16 * 32];      // fragment-major bf16 codebook (512KB)

// ---------------------------------------------------------------------------
__device__ __forceinline__ uint32_t smem_u32(const void* p) {
    uint32_t a;
    asm("{ .reg .u64 t; cvta.to.shared.u64 t, %1; cvt.u32.u64 %0, t; }" : "=r"(a) : "l"(p));
    return a;
}
__device__ __forceinline__ void mma16816(float* c, uint32_t a0, uint32_t a1,
                                         uint32_t a2, uint32_t a3,
                                         uint32_t b0, uint32_t b1) {
    asm volatile(
        "mma.sync.aligned.m16n8k16.row.col.f32.bf16.bf16.f32 "
        "{%0,%1,%2,%3}, {%4,%5,%6,%7}, {%8,%9}, {%0,%1,%2,%3};"
        : "+f"(c[0]), "+f"(c[1]), "+f"(c[2]), "+f"(c[3])
        : "r"(a0), "r"(a1), "r"(a2), "r"(a3), "r"(b0), "r"(b1));
}
#define CP16(saddr, gptr) \
    asm volatile("cp.async.cg.shared.global [%0], [%1], 16;" :: "r"(saddr), "l"(gptr) : "memory")
#define CP_COMMIT() asm volatile("cp.async.commit_group;" ::: "memory")
#define CP_WAIT0()  asm volatile("cp.async.wait_group 0;" ::: "memory")

__device__ __forceinline__ uint32_t pack_bf16x2(float lo, float hi) {
    uint16_t l = __bfloat16_as_ushort(__float2bfloat16(lo));
    uint16_t h = __bfloat16_as_ushort(__float2bfloat16(hi));
    return (uint32_t)l | ((uint32_t)h << 16);
}

// ---------------------------------------------------------------------------
// w2[k] = sum_d w[k,d]^2 (square-then-add, matching reference)
__global__ void vq_w2(const float* __restrict__ w) {
    int k = blockIdx.x * 8 + (threadIdx.x >> 5);
    int lane = threadIdx.x & 31;
    if (k >= KN) return;
    const float* row = w + (size_t)k * DN;
    float s = 0.f;
    #pragma unroll
    for (int d = lane; d < DN; d += 32) {
        float v = row[d];
        s = __fadd_rn(s, __fmul_rn(v, v));
    }
    #pragma unroll
    for (int o = 16; o > 0; o >>= 1) s += __shfl_xor_sync(0xffffffffu, s, o);
    if (lane == 0) g_w2[k] = s;
}

// x2[n] = sum_d x[b,d,hw]^2 ; also zero g_ccnt
__global__ void vq_x2(const float* __restrict__ x) {
    int b  = blockIdx.y;
    int hw = blockIdx.x * blockDim.x + threadIdx.x;
    const float* base = x + (size_t)b * DN * HWN + hw;
    float s = 0.f;
    #pragma unroll 8
    for (int d = 0; d < DN; d++) {
        float v = base[(size_t)d * HWN];
        s = __fadd_rn(s, __fmul_rn(v, v));
    }
    int n = b * HWN + hw;
    g_x2[n] = s;
    g_ccnt[n] = 0;
}

// Fragment-major bf16 codebook: g_bf[((c*16+ks)*16+nt)*32+lane] = {b0,b1}
__global__ void vq_wfrag(const float* __restrict__ w) {
    int i = blockIdx.x * 256 + threadIdx.x;   // 0..65535
    int lane = i & 31, nt = (i >> 5) & 15, ks = (i >> 9) & 15, c = i >> 13;
    int gid = lane >> 2, tq = lane & 3;
    int k = c * 128 + nt * 8 + gid;
    const float* row = w + (size_t)k * DN + ks * 16;
    uint32_t b0 = pack_bf16x2(row[2 * tq], row[2 * tq + 1]);
    uint32_t b1 = pack_bf16x2(row[2 * tq + 8], row[2 * tq + 9]);
    g_bf[i] = make_uint2(b0, b1);
}

// Transpose x[b][d][hw] -> Xt[n][d] (fp32 + bf16), n = b*HWN + hw
__global__ void vq_xt(const float* __restrict__ x) {
    __shared__ float t[32][33];
    int b   = blockIdx.z;
    int d0  = blockIdx.y * 32;
    int hw0 = blockIdx.x * 32;
    int tx = threadIdx.x, ty = threadIdx.y;  // 32 x 8
    #pragma unroll
    for (int r = 0; r < 4; r++)
        t[ty + 8 * r][tx] = x[(size_t)b * DN * HWN + (size_t)(d0 + ty + 8 * r) * HWN + hw0 + tx];
    __syncthreads();
    #pragma unroll
    for (int r = 0; r < 4; r++) {
        int n = b * HWN + hw0 + ty + 8 * r;
        float v = t[tx][ty + 8 * r];
        g_xt[(size_t)n * DN + d0 + tx] = v;
        g_xb[(size_t)n * DN + d0 + tx] = __float2bfloat16(v);
    }
}

// ---------------------------------------------------------------------------
// P1: bf16 HMMA approx-d2 + candidate emission (running-global-min thresholds).
#define SMA   0
#define SMB0  69632
#define SMB1  135168
#define SMW2  200704
#define SMCM  204800
#define SMEM_P1 205312

__global__ __launch_bounds__(256, 1) void vq_p1() {
    extern __shared__ __align__(16) char smem[];
    char*  A     = smem + SMA;
    float* w2s   = (float*)(smem + SMW2);
    int*   cminI = (int*)(smem + SMCM);
    const uint32_t sb = smem_u32(smem);

    const int tid  = threadIdx.x;
    const int wid  = tid >> 5, lane = tid & 31;
    const int gid  = lane >> 2, tq = lane & 3;
    const int wm   = wid & 3, wn = wid >> 2;
    const int m0   = blockIdx.x * 128;

    // Prologue: start async fill of B chunk 0
    {
        const char* src = (const char*)g_bf;
        #pragma unroll
        for (int j = 0; j < 16; j++)
            CP16(sb + SMB0 + (tid + j * 256) * 16, src + (tid + j * 256) * 16);
        CP_COMMIT();
    }

    // Fill A tile: pair-permuted rows (elems {2t,2t+1,2t+8,2t+9} adjacent)
    #pragma unroll
    for (int i = tid; i < 2048; i += 256) {
        int r = i >> 4, ks = i & 15;
        const uint4* src = (const uint4*)(g_xb + (size_t)(m0 + r) * DN + ks * 16);
        uint4 U0 = src[0], U1 = src[1];
        char* dst = A + r * AS + ks * 32;
        *(uint4*)dst        = make_uint4(U0.x, U1.x, U0.y, U1.y);
        *(uint4*)(dst + 16) = make_uint4(U0.z, U1.z, U0.w, U1.w);
    }
    #pragma unroll
    for (int i = tid; i < KN; i += 256) w2s[i] = g_w2[i];
    if (tid < 128) cminI[tid] = 0x7F7FFFFF;

    const int ra0 = wm * 16 + gid, rb0 = ra0 + 8;
    const int ra1 = (wm + 4) * 16 + gid, rb1 = ra1 + 8;
    const float x2a0 = g_x2[m0 + ra0], x2b0 = g_x2[m0 + rb0];
    const float x2a1 = g_x2[m0 + ra1], x2b1 = g_x2[m0 + rb1];

    const char* Ab0 = A + ra0 * AS + tq * 8;
    const char* Ab1 = A + ra1 * AS + tq * 8;

    for (int c = 0; c < 8; c++) {
        CP_WAIT0();
        __syncthreads();   // B[c] ready; A tile ready (c==0); prev compute done

        if (c < 7) {       // start fill of B[c+1] into the other buffer
            const char* src = (const char*)(g_bf + (size_t)(c + 1) * 8192);
            uint32_t dstb = sb + (((c + 1) & 1) ? SMB1 : SMB0);
            #pragma unroll
            for (int j = 0; j < 16; j++)
                CP16(dstb + (tid + j * 256) * 16, src + (tid + j * 256) * 16);
            CP_COMMIT();
        }

        const uint2* Bbuf = (const uint2*)(smem + ((c & 1) ? SMB1 : SMB0));
        float acc[2][8][4];
        #pragma unroll
        for (int mt = 0; mt < 2; mt++)
            #pragma unroll
            for (int nt = 0; nt < 8; nt++)
                acc[mt][nt][0] = acc[mt][nt][1] = acc[mt][nt][2] = acc[mt][nt][3] = 0.f;

        #pragma unroll
        for (int ks = 0; ks < 16; ks++) {
            uint2 av0 = *(const uint2*)(Ab0 + ks * 32);
            uint2 av1 = *(const uint2*)(Ab0 + 8 * AS + ks * 32);
            uint2 av2 = *(const uint2*)(Ab1 + ks * 32);
            uint2 av3 = *(const uint2*)(Ab1 + 8 * AS + ks * 32);
            const uint2* bp = Bbuf + (size_t)(ks * 16 + wn * 8) * 32 + lane;
            #pragma unroll
            for (int nt = 0; nt < 8; nt++) {
                uint2 b = bp[nt * 32];
                mma16816(acc[0][nt], av0.x, av1.x, av0.y, av1.y, b.x, b.y);
                mma16816(acc[1][nt], av2.x, av3.x, av2.y, av3.y, b.x, b.y);
            }
        }

        // Scores + warp-local row mins
        float mna0 = 3.4e38f, mnb0 = 3.4e38f, mna1 = 3.4e38f, mnb1 = 3.4e38f;
        #pragma unroll
        for (int nt = 0; nt < 8; nt++) {
            int col = c * 128 + (wn * 8 + nt) * 8 + tq * 2;
            float w20 = w2s[col], w21 = w2s[col + 1];
            float d;
            d = fmaf(-2.f, acc[0][nt][0], x2a0) + w20; acc[0][nt][0] = d; mna0 = fminf(mna0, d);
            d = fmaf(-2.f, acc[0][nt][1], x2a0) + w21; acc[0][nt][1] = d; mna0 = fminf(mna0, d);
            d = fmaf(-2.f, acc[0][nt][2], x2b0) + w20; acc[0][nt][2] = d; mnb0 = fminf(mnb0, d);
            d = fmaf(-2.f, acc[0][nt][3], x2b0) + w21; acc[0][nt][3] = d; mnb0 = fminf(mnb0, d);
            d = fmaf(-2.f, acc[1][nt][0], x2a1) + w20; acc[1][nt][0] = d; mna1 = fminf(mna1, d);
            d = fmaf(-2.f, acc[1][nt][1], x2a1) + w21; acc[1][nt][1] = d; mna1 = fminf(mna1, d);
            d = fmaf(-2.f, acc[1][nt][2], x2b1) + w20; acc[1][nt][2] = d; mnb1 = fminf(mnb1, d);
            d = fmaf(-2.f, acc[1][nt][3], x2b1) + w21; acc[1][nt][3] = d; mnb1 = fminf(mnb1, d);
        }
        #pragma unroll
        for (int o = 1; o <= 2; o <<= 1) {
            mna0 = fminf(mna0, __shfl_xor_sync(0xffffffffu, mna0, o));
            mnb0 = fminf(mnb0, __shfl_xor_sync(0xffffffffu, mnb0, o));
            mna1 = fminf(mna1, __shfl_xor_sync(0xffffffffu, mna1, o));
            mnb1 = fminf(mnb1, __shfl_xor_sync(0xffffffffu, mnb1, o));
        }
        if (tq == 0) {
            atomicMin(&cminI[ra0], __float_as_int(mna0));
            atomicMin(&cminI[rb0], __float_as_int(mnb0));
            atomicMin(&cminI[ra1], __float_as_int(mna1));
            atomicMin(&cminI[rb1], __float_as_int(mnb1));
        }
        __syncthreads();  // running global min (all warps, all chunks so far) visible

        // Emit with RUNNING-GLOBAL-min thresholds (tight superset; see proof)
        const float ta0 = __int_as_float(cminI[ra0]) + MARGIN;
        const float tb0 = __int_as_float(cminI[rb0]) + MARGIN;
        const float ta1 = __int_as_float(cminI[ra1]) + MARGIN;
        const float tb1 = __int_as_float(cminI[rb1]) + MARGIN;
        #pragma unroll
        for (int nt = 0; nt < 8; nt++) {
            int col = c * 128 + (wn * 8 + nt) * 8 + tq * 2;
            #pragma unroll
            for (int v = 0; v < 2; v++) {
                if (acc[0][nt][v] <= ta0) {
                    int p = atomicAdd(&g_ccnt[m0 + ra0], 1);
                    if (p < CAND_MAX)
                        g_cand[(size_t)(m0 + ra0) * CAND_MAX + p] =
                            make_uint2(__float_as_uint(acc[0][nt][v]), col + v);
                }
                if (acc[0][nt][2 + v] <= tb0) {
                    int p = atomicAdd(&g_ccnt[m0 + rb0], 1);
                    if (p < CAND_MAX)
                        g_cand[(size_t)(m0 + rb0) * CAND_MAX + p] =
                            make_uint2(__float_as_uint(acc[0][nt][2 + v]), col + v);
                }
                if (acc[1][nt][v] <= ta1) {
                    int p = atomicAdd(&g_ccnt[m0 + ra1], 1);
                    if (p < CAND_MAX)
                        g_cand[(size_t)(m0 + ra1) * CAND_MAX + p] =
                            make_uint2(__float_as_uint(acc[1][nt][v]), col + v);
                }
                if (acc[1][nt][2 + v] <= tb1) {
                    int p = atomicAdd(&g_ccnt[m0 + rb1], 1);
                    if (p < CAND_MAX)
                        g_cand[(size_t)(m0 + rb1) * CAND_MAX + p] =
                            make_uint2(__float_as_uint(acc[1][nt][2 + v]), col + v);
                }
            }
        }
    }

    __syncthreads();
    if (tid < 128) g_cminF[m0 + tid] = __int_as_float(cminI[tid]);
}

// ---------------------------------------------------------------------------
// P3: exact fp32 rescore. One warp per query. Overflow -> full exact scan.
__global__ __launch_bounds__(256) void vq_p3(const float* __restrict__ w) {
    const int wid = threadIdx.x >> 5, lane = threadIdx.x & 31;
    const int q = blockIdx.x * 8 + wid;
    const int rawcnt = g_ccnt[q];
    const float* xr = g_xt + (size_t)q * DN;
    const float x2v = g_x2[q];
    unsigned long long best = 0xFFFFFFFFFFFFFFFFULL;

    if (rawcnt <= CAND_MAX) {
        const float thr = g_cminF[q] + MARGIN;
        for (int c = 0; c < rawcnt; c++) {
            uint2 e = g_cand[(size_t)q * CAND_MAX + c];
            if (__uint_as_float(e.x) > thr) continue;
            unsigned int k = e.y;
            const float* wr = w + (size_t)k * DN;
            float s = 0.f;
            #pragma unroll
            for (int d = lane; d < DN; d += 32)
                s = fmaf(xr[d], wr[d], s);
            #pragma unroll
            for (int o = 16; o > 0; o >>= 1) s += __shfl_xor_sync(0xffffffffu, s, o);
            float d2 = __fadd_rn(__fsub_rn(x2v, __fmul_rn(2.0f, s)), g_w2[k]);
            unsigned int bits = __float_as_uint(d2);
            bits = (bits & 0x80000000u) ? ~bits : (bits | 0x80000000u);
            best = min(best, ((unsigned long long)bits << 32) | k);
        }
    } else {
        // Safety fallback: full exact scan (guarantees g_best is always set)
        for (int k = 0; k < KN; k++) {
            const float* wr = w + (size_t)k * DN;
            float s = 0.f;
            #pragma unroll
            for (int d = lane; d < DN; d += 32)
                s = fmaf(xr[d], wr[d], s);
            #pragma unroll
            for (int o = 16; o > 0; o >>= 1) s += __shfl_xor_sync(0xffffffffu, s, o);
            float d2 = __fadd_rn(__fsub_rn(x2v, __fmul_rn(2.0f, s)), g_w2[k]);
            unsigned int bits = __float_as_uint(d2);
            bits = (bits & 0x80000000u) ? ~bits : (bits | 0x80000000u);
            best = min(best, ((unsigned long long)bits << 32) | (unsigned int)k);
        }
    }
    if (lane == 0) g_best[q] = best;
}

// ---------------------------------------------------------------------------
// Gather: out[b,d,hw] = weight[idx[n], d]
__global__ void vq_gather(const float* __restrict__ w, float* __restrict__ out) {
    __shared__ float codes[32][DN + 1];
    const int b   = blockIdx.y;
    const int hw0 = blockIdx.x * 32;
    const int tid = threadIdx.x;  // 256
    for (int s = 0; s < 32; s++) {
        unsigned int idx = (unsigned int)(g_best[b * HWN + hw0 + s] & 0xFFFFFFFFu);
        codes[s][tid] = w[(size_t)idx * DN + tid];
    }
    __syncthreads();
    const int c    = tid & 31;
    const int dgrp = tid >> 5;
    float* ob = out + (size_t)b * DN * HWN + hw0;
    for (int d = dgrp; d < DN; d += 8)
        ob[(size_t)d * HWN + c] = codes[c][d];
}

// ---------------------------------------------------------------------------
extern "C" void kernel_launch(void* const* d_in, const int* in_sizes, int n_in,
                              void* d_out, int out_size) {
    const float* x = (const float*)d_in[0];   // [32,256,32,32] fp32
    const float* w = (const float*)d_in[1];   // [1024,256] fp32
    float* out = (float*)d_out;

    cudaFuncSetAttribute(vq_p1, cudaFuncAttributeMaxDynamicSharedMemorySize, SMEM_P1);

    vq_w2<<<KN / 8, 256>>>(w);
    {
        dim3 g(HWN / 256, BN);
        vq_x2<<<g, 256>>>(x);
    }
    vq_wfrag<<<65536 / 256, 256>>>(w);
    {
        dim3 g(HWN / 32, DN / 32, BN);
        dim3 blk(32, 8);
        vq_xt<<<g, blk>>>(x);
    }
    vq_p1<<<NN / 128, 256, SMEM_P1>>>();
    vq_p3<<<NN / 8, 256>>>(w);
    {
        dim3 g(HWN / 32, BN);
        vq_gather<<<g, 256>>>(w, out);
    }
}

// round 13
// speedup vs baseline: 1.4695x; 1.4695x over previous
#include <cuda_runtime.h>
#include <cuda_bf16.h>
#include <cstdint>

// Problem constants
#define BN   32
#define DN   256
#define KN   1024
#define HWN  1024
#define NN   32768

#define LIST_CAP 48
#define CAND_MAX 48
#define MARGIN   4.0e-3f   // > 2x worst-case bf16 d2 error

// ---------------------------------------------------------------------------
// Device-global scratch (no allocation allowed)
__device__ unsigned long long g_best[NN];
__device__ float g_w2[KN];
__device__ float g_x2[NN];
__device__ float g_cminF[NN];                 // per-query global approx min
__device__ __nv_bfloat16 g_xb[NN * DN];       // x bf16, PAIR-PERMUTED rows [n][pd]
__device__ float g_xt[NN * DN];               // x transposed fp32 [n][d]
__device__ int g_ccnt[NN];
__device__ uint2 g_cand[NN * CAND_MAX];       // (approx d2 bits, code idx)
__device__ uint2 g_bf[8 * 16 * 16 * 32];      // fragment-major bf16 codebook (512KB)

// ---------------------------------------------------------------------------
__device__ __forceinline__ uint32_t smem_u32(const void* p) {
    uint32_t a;
    asm("{ .reg .u64 t; cvta.to.shared.u64 t, %1; cvt.u32.u64 %0, t; }" : "=r"(a) : "l"(p));
    return a;
}
__device__ __forceinline__ void mma16816(float* c, uint32_t a0, uint32_t a1,
                                         uint32_t a2, uint32_t a3,
                                         uint32_t b0, uint32_t b1) {
    asm volatile(
        "mma.sync.aligned.m16n8k16.row.col.f32.bf16.bf16.f32 "
        "{%0,%1,%2,%3}, {%4,%5,%6,%7}, {%8,%9}, {%0,%1,%2,%3};"
        : "+f"(c[0]), "+f"(c[1]), "+f"(c[2]), "+f"(c[3])
        : "r"(a0), "r"(a1), "r"(a2), "r"(a3), "r"(b0), "r"(b1));
}
#define CP16(saddr, gptr) \
    asm volatile("cp.async.cg.shared.global [%0], [%1], 16;" :: "r"(saddr), "l"(gptr) : "memory")
#define CP_COMMIT() asm volatile("cp.async.commit_group;" ::: "memory")
#define CP_WAIT0()  asm volatile("cp.async.wait_group 0;" ::: "memory")

__device__ __forceinline__ uint32_t pack_bf16x2(float lo, float hi) {
    uint16_t l = __bfloat16_as_ushort(__float2bfloat16(lo));
    uint16_t h = __bfloat16_as_ushort(__float2bfloat16(hi));
    return (uint32_t)l | ((uint32_t)h << 16);
}

// ---------------------------------------------------------------------------
// w2[k] = sum_d w[k,d]^2 (square-then-add, matching reference)
__global__ void vq_w2(const float* __restrict__ w) {
    int k = blockIdx.x * 8 + (threadIdx.x >> 5);
    int lane = threadIdx.x & 31;
    if (k >= KN) return;
    const float* row = w + (size_t)k * DN;
    float s = 0.f;
    #pragma unroll
    for (int d = lane; d < DN; d += 32) {
        float v = row[d];
        s = __fadd_rn(s, __fmul_rn(v, v));
    }
    #pragma unroll
    for (int o = 16; o > 0; o >>= 1) s += __shfl_xor_sync(0xffffffffu, s, o);
    if (lane == 0) g_w2[k] = s;
}

// x2[n] = sum_d x[b,d,hw]^2
__global__ void vq_x2(const float* __restrict__ x) {
    int b  = blockIdx.y;
    int hw = blockIdx.x * blockDim.x + threadIdx.x;
    const float* base = x + (size_t)b * DN * HWN + hw;
    float s = 0.f;
    #pragma unroll 8
    for (int d = 0; d < DN; d++) {
        float v = base[(size_t)d * HWN];
        s = __fadd_rn(s, __fmul_rn(v, v));
    }
    g_x2[b * HWN + hw] = s;
}

// Fragment-major bf16 codebook: g_bf[((c*16+ks)*16+nt)*32+lane] = {b0,b1}
__global__ void vq_wfrag(const float* __restrict__ w) {
    int i = blockIdx.x * 256 + threadIdx.x;   // 0..65535
    int lane = i & 31, nt = (i >> 5) & 15, ks = (i >> 9) & 15, c = i >> 13;
    int gid = lane >> 2, tq = lane & 3;
    int k = c * 128 + nt * 8 + gid;
    const float* row = w + (size_t)k * DN + ks * 16;
    uint32_t b0 = pack_bf16x2(row[2 * tq], row[2 * tq + 1]);
    uint32_t b1 = pack_bf16x2(row[2 * tq + 8], row[2 * tq + 9]);
    g_bf[i] = make_uint2(b0, b1);
}

// Transpose x[b][d][hw] -> g_xt[n][d] fp32 and g_xb[n][pd] bf16 pair-permuted:
// pd = ks*16 + tq*4 + hi*2 + par where d = ks*16 + hi*8 + tq*2 + par.
// A lane can then load its m16n8k16 A-fragment pair {a0,a2} as one uint2.
__global__ void vq_xt(const float* __restrict__ x) {
    __shared__ float t[32][33];
    int b   = blockIdx.z;
    int d0  = blockIdx.y * 32;
    int hw0 = blockIdx.x * 32;
    int tx = threadIdx.x, ty = threadIdx.y;  // 32 x 8
    #pragma unroll
    for (int r = 0; r < 4; r++)
        t[ty + 8 * r][tx] = x[(size_t)b * DN * HWN + (size_t)(d0 + ty + 8 * r) * HWN + hw0 + tx];
    __syncthreads();
    #pragma unroll
    for (int r = 0; r < 4; r++) {
        int n = b * HWN + hw0 + ty + 8 * r;
        int d = d0 + tx;
        float v = t[tx][ty + 8 * r];
        g_xt[(size_t)n * DN + d] = v;
        int pd = (d & ~15) | (((d >> 1) & 3) << 2) | (((d >> 3) & 1) << 1) | (d & 1);
        g_xb[(size_t)n * DN + pd] = __float2bfloat16(v);
    }
}

// ---------------------------------------------------------------------------
// P1: bf16 HMMA approx-d2 + candidate emission (R9 control flow).
// 256 CTAs x 256 thr. Warp wid -> 16 query rows [wid*16, wid*16+16),
// covering all 128 codes of each chunk (16 n-tiles). A frags in registers.
#define SMB0  0
#define SMB1  65536
#define SMW2  131072
#define SMCM  135168
#define SMCC  135680
#define SMLS  136192
#define SMEM_P1 185344

__global__ __launch_bounds__(256, 1) void vq_p1() {
    extern __shared__ __align__(16) char smem[];
    float* w2s   = (float*)(smem + SMW2);
    int*   cminI = (int*)(smem + SMCM);
    int*   ccnt  = (int*)(smem + SMCC);
    uint2* clist = (uint2*)(smem + SMLS);
    const uint32_t sb = smem_u32(smem);

    const int tid  = threadIdx.x;
    const int wid  = tid >> 5, lane = tid & 31;
    const int gid  = lane >> 2, tq = lane & 3;
    const int m0   = blockIdx.x * 128;
    const int ra   = wid * 16 + gid, rb = ra + 8;

    // Prologue: start async fill of B chunk 0
    {
        const char* src = (const char*)g_bf;
        #pragma unroll
        for (int j = 0; j < 16; j++)
            CP16(sb + SMB0 + (tid + j * 256) * 16, src + (tid + j * 256) * 16);
        CP_COMMIT();
    }

    // Preload A fragments into registers (pair-permuted g_xb rows)
    uint2 afA[16], afB[16];
    {
        const __nv_bfloat16* xa = g_xb + (size_t)(m0 + ra) * DN + tq * 4;
        const __nv_bfloat16* xb = g_xb + (size_t)(m0 + rb) * DN + tq * 4;
        #pragma unroll
        for (int ks = 0; ks < 16; ks++) {
            afA[ks] = *(const uint2*)(xa + ks * 16);
            afB[ks] = *(const uint2*)(xb + ks * 16);
        }
    }

    #pragma unroll
    for (int i = tid; i < KN; i += 256) w2s[i] = g_w2[i];
    if (tid < 128) { cminI[tid] = 0x7F7FFFFF; ccnt[tid] = 0; }

    const float x2a = g_x2[m0 + ra], x2b = g_x2[m0 + rb];

    for (int c = 0; c < 8; c++) {
        CP_WAIT0();
        __syncthreads();   // B[c] + (c==0: w2s/ccnt init) visible; prev compute done

        if (c < 7) {       // prefetch B[c+1] into the other buffer
            const char* src = (const char*)(g_bf + (size_t)(c + 1) * 8192);
            uint32_t dstb = sb + (((c + 1) & 1) ? SMB1 : SMB0);
            #pragma unroll
            for (int j = 0; j < 16; j++)
                CP16(dstb + (tid + j * 256) * 16, src + (tid + j * 256) * 16);
            CP_COMMIT();
        }

        const uint2* Bbuf = (const uint2*)(smem + ((c & 1) ? SMB1 : SMB0));
        float acc[16][4];
        #pragma unroll
        for (int nt = 0; nt < 16; nt++)
            acc[nt][0] = acc[nt][1] = acc[nt][2] = acc[nt][3] = 0.f;

        #pragma unroll
        for (int ks = 0; ks < 16; ks++) {
            const uint2* bp = Bbuf + (size_t)(ks * 16) * 32 + lane;
            #pragma unroll
            for (int nt = 0; nt < 16; nt++) {
                uint2 b = bp[nt * 32];
                mma16816(acc[nt], afA[ks].x, afB[ks].x, afA[ks].y, afB[ks].y, b.x, b.y);
            }
        }

        // Epilogue: scores, chunk-local row mins (warp covers full chunk)
        float mna = 3.4e38f, mnb = 3.4e38f;
        #pragma unroll
        for (int nt = 0; nt < 16; nt++) {
            int col = c * 128 + nt * 8 + tq * 2;
            float w20 = w2s[col], w21 = w2s[col + 1];
            float d;
            d = fmaf(-2.f, acc[nt][0], x2a) + w20; acc[nt][0] = d; mna = fminf(mna, d);
            d = fmaf(-2.f, acc[nt][1], x2a) + w21; acc[nt][1] = d; mna = fminf(mna, d);
            d = fmaf(-2.f, acc[nt][2], x2b) + w20; acc[nt][2] = d; mnb = fminf(mnb, d);
            d = fmaf(-2.f, acc[nt][3], x2b) + w21; acc[nt][3] = d; mnb = fminf(mnb, d);
        }
        #pragma unroll
        for (int o = 1; o <= 2; o <<= 1) {
            mna = fminf(mna, __shfl_xor_sync(0xffffffffu, mna, o));
            mnb = fminf(mnb, __shfl_xor_sync(0xffffffffu, mnb, o));
        }
        if (tq == 0) {
            atomicMin(&cminI[ra], __float_as_int(mna));
            atomicMin(&cminI[rb], __float_as_int(mnb));
        }
        // Emit vs chunk-local min (>= global min -> sound superset); smem lists
        const float ta = mna + MARGIN, tb = mnb + MARGIN;
        #pragma unroll
        for (int nt = 0; nt < 16; nt++) {
            int col = c * 128 + nt * 8 + tq * 2;
            #pragma unroll
            for (int v = 0; v < 2; v++) {
                if (acc[nt][v] <= ta) {
                    int p = atomicAdd(&ccnt[ra], 1);
                    if (p < LIST_CAP)
                        clist[ra * LIST_CAP + p] = make_uint2(__float_as_uint(acc[nt][v]), col + v);
                }
                if (acc[nt][2 + v] <= tb) {
                    int p = atomicAdd(&ccnt[rb], 1);
                    if (p < LIST_CAP)
                        clist[rb * LIST_CAP + p] = make_uint2(__float_as_uint(acc[nt][2 + v]), col + v);
                }
            }
        }
    }

    __syncthreads();
    // Final refilter vs GLOBAL approx min; overflow -> sentinel (P3 full scan)
    if (tid < 128) {
        int m = m0 + tid;
        float gm = __int_as_float(cminI[tid]);
        g_cminF[m] = gm;
        int raw = ccnt[tid];
        if (raw > LIST_CAP) {
            g_ccnt[m] = 0x7FFFFFFF;
        } else {
            float thr = gm + MARGIN;
            int out = 0;
            for (int i = 0; i < raw; i++) {
                uint2 e = clist[tid * LIST_CAP + i];
                if (__uint_as_float(e.x) <= thr)
                    g_cand[(size_t)m * CAND_MAX + (out++)] = e;
            }
            g_ccnt[m] = out;
        }
    }
}

// ---------------------------------------------------------------------------
// P3: exact fp32 rescore. One warp per query. Sentinel -> full exact scan.
__global__ __launch_bounds__(256) void vq_p3(const float* __restrict__ w) {
    const int wid = threadIdx.x >> 5, lane = threadIdx.x & 31;
    const int q = blockIdx.x * 8 + wid;
    const int cnt = g_ccnt[q];
    const float* xr = g_xt + (size_t)q * DN;
    const float x2v = g_x2[q];
    unsigned long long best = 0xFFFFFFFFFFFFFFFFULL;

    if (cnt != 0x7FFFFFFF) {
        for (int c = 0; c < cnt; c++) {
            unsigned int k = g_cand[(size_t)q * CAND_MAX + c].y;
            const float* wr = w + (size_t)k * DN;
            float s = 0.f;
            #pragma unroll
            for (int d = lane; d < DN; d += 32)
                s = fmaf(xr[d], wr[d], s);
            #pragma unroll
            for (int o = 16; o > 0; o >>= 1) s += __shfl_xor_sync(0xffffffffu, s, o);
            float d2 = __fadd_rn(__fsub_rn(x2v, __fmul_rn(2.0f, s)), g_w2[k]);
            unsigned int bits = __float_as_uint(d2);
            bits = (bits & 0x80000000u) ? ~bits : (bits | 0x80000000u);
            best = min(best, ((unsigned long long)bits << 32) | k);
        }
    } else {
        // Safety fallback: full exact scan (guarantees g_best is always set)
        for (int k = 0; k < KN; k++) {
            const float* wr = w + (size_t)k * DN;
            float s = 0.f;
            #pragma unroll
            for (int d = lane; d < DN; d += 32)
                s = fmaf(xr[d], wr[d], s);
            #pragma unroll
            for (int o = 16; o > 0; o >>= 1) s += __shfl_xor_sync(0xffffffffu, s, o);
            float d2 = __fadd_rn(__fsub_rn(x2v, __fmul_rn(2.0f, s)), g_w2[k]);
            unsigned int bits = __float_as_uint(d2);
            bits = (bits & 0x80000000u) ? ~bits : (bits | 0x80000000u);
            best = min(best, ((unsigned long long)bits << 32) | (unsigned int)k);
        }
    }
    if (lane == 0) g_best[q] = best;
}

// ---------------------------------------------------------------------------
// Gather: out[b,d,hw] = weight[idx[n], d]
__global__ void vq_gather(const float* __restrict__ w, float* __restrict__ out) {
    __shared__ float codes[32][DN + 1];
    const int b   = blockIdx.y;
    const int hw0 = blockIdx.x * 32;
    const int tid = threadIdx.x;  // 256
    for (int s = 0; s < 32; s++) {
        unsigned int idx = (unsigned int)(g_best[b * HWN + hw0 + s] & 0xFFFFFFFFu);
        codes[s][tid] = w[(size_t)idx * DN + tid];
    }
    __syncthreads();
    const int c    = tid & 31;
    const int dgrp = tid >> 5;
    float* ob = out + (size_t)b * DN * HWN + hw0;
    for (int d = dgrp; d < DN; d += 8)
        ob[(size_t)d * HWN + c] = codes[c][d];
}

// ---------------------------------------------------------------------------
extern "C" void kernel_launch(void* const* d_in, const int* in_sizes, int n_in,
                              void* d_out, int out_size) {
    const float* x = (const float*)d_in[0];   // [32,256,32,32] fp32
    const float* w = (const float*)d_in[1];   // [1024,256] fp32
    float* out = (float*)d_out;

    cudaFuncSetAttribute(vq_p1, cudaFuncAttributeMaxDynamicSharedMemorySize, SMEM_P1);

    vq_w2<<<KN / 8, 256>>>(w);
    {
        dim3 g(HWN / 256, BN);
        vq_x2<<<g, 256>>>(x);
    }
    vq_wfrag<<<65536 / 256, 256>>>(w);
    {
        dim3 g(HWN / 32, DN / 32, BN);
        dim3 blk(32, 8);
        vq_xt<<<g, blk>>>(x);
    }
    vq_p1<<<NN / 128, 256, SMEM_P1>>>();
    vq_p3<<<NN / 8, 256>>>(w);
    {
        dim3 g(HWN / 32, BN);
        vq_gather<<<g, 256>>>(w, out);
    }
}